// round 2
// baseline (speedup 1.0000x reference)
#include <cuda_runtime.h>

#define PI_D 3.14159265358979323846

// ---------------- constants / scratch ----------------
__device__ __constant__ int c_OFF[8] = {0,1,10,35,84,165,286,455};

__device__ double g_qw[8], g_beta[8];
__device__ double g_c8a[8], g_c8b[8], g_c8g[8];
__device__ double g_X0[7][169], g_X1[7][169];

__device__ float g_EY[7][16][169];   // exp(2pi k/16 * X1) (alpha == gamma grid)
__device__ float g_EB[7][8][169];    // exp(beta_ib * X0)
__device__ float g_RA[7][8][169];    // c8 exp(a*X1)
__device__ float g_RB[7][8][169];    // c8 exp(b*X0)
__device__ float g_RG[7][8][169];    // c8 exp(g*X1)
__device__ float g_Fab[7][128][169]; // EY[ia] @ EB[ib]

__device__ float g_DIN[2048][10];
__device__ float g_DOUTW[2048][455];
__device__ float g_C8W[8][455];
__device__ float g_M2T[7280][512];   // fused proj_2 + C8 operator (K-major)

__device__ float g_featin[8192][10];
__device__ float g_sig[8192][2048];
__device__ float g_feat[8192][455];
__device__ float g_part[8][512][512];

// ================= setup: GL nodes + C8 Euler angles =================
__global__ void k_init() {
    int t = threadIdx.x;
    if (t < 4) {
        // Newton on P8; i = t+1 gives descending positive roots
        double x = cos(PI_D * (t + 0.75) / 8.5);
        double pp = 1.0;
        for (int it = 0; it < 60; it++) {
            double p0 = 1.0, p1 = x;
            for (int k = 2; k <= 8; k++) {
                double p2 = ((2.0 * k - 1.0) * x * p1 - (k - 1.0) * p0) / k;
                p0 = p1; p1 = p2;
            }
            pp = 8.0 * (x * p1 - p0) / (x * x - 1.0);
            x -= p1 / pp;
        }
        double w = 2.0 / ((1.0 - x * x) * pp * pp);
        // ascending node order (matches numpy leggauss)
        g_qw[t] = w / 512.0;  g_qw[7 - t] = w / 512.0;
        g_beta[t] = acos(-x); g_beta[7 - t] = acos(x);
    }
    if (t >= 8 && t < 16) {
        int i = t - 8;
        double th = 2.0 * PI_D * i / 8.0;
        double st = sin(th), ct = cos(th);
        double cb = fmin(1.0, fmax(-1.0, ct));
        double b = acos(cb);
        double a = atan2(st, 0.0);
        double sa = sin(a), ca = cos(a);
        // R = (my(a)@mx(b))^T @ M ; R00 = ca*ct, R02 = -sa (exact algebra)
        double g = atan2(-sa, ca * ct);
        g_c8a[i] = a; g_c8b[i] = b; g_c8g[i] = g;
    }
}

// ============ setup: real so(3) generators X0 (Jx), X1 (Jy) per l ============
__global__ void k_gen() {
    int l = blockIdx.x;
    int d = 2 * l + 1, dd = d * d;
    __shared__ double Qre[169], Qim[169], Cre[169], Cim[169];
    int t = threadIdx.x;
    if (t < dd) { Qre[t] = 0.0; Qim[t] = 0.0; }
    __syncthreads();
    if (t == 0) {
        const double r2 = 0.7071067811865475244;
        for (int m = -l; m < 0; m++) {
            Qre[(l + m) * d + (l - m)] = r2;     // q[l+m, l+|m|]
            Qim[(l + m) * d + (l + m)] = -r2;    // q[l+m, l-|m|] = -i/sqrt2
        }
        Qre[l * d + l] = 1.0;
        for (int m = 1; m <= l; m++) {
            double s = (m & 1) ? -1.0 : 1.0;
            Qre[(l + m) * d + (l + m)] = s * r2;
            Qim[(l + m) * d + (l - m)] = s * r2; // i*(-1)^m/sqrt2
        }
    }
    __syncthreads();
    // multiply by (-i)^l
    if (t < dd) {
        double re = Qre[t], im = Qim[t];
        switch (l & 3) {
            case 1: Qre[t] = im;  Qim[t] = -re; break;
            case 2: Qre[t] = -re; Qim[t] = -im; break;
            case 3: Qre[t] = -im; Qim[t] = re;  break;
            default: break;
        }
    }
    __syncthreads();
    // C = Su0 * Q (Su0 antisymmetric bidiagonal)
    if (t < dd) {
        int k = t / d, b = t % d;
        double cr = 0.0, ci = 0.0;
        if (k >= 1) {
            double mi = (double)(k - 1 - l);
            double s = sqrt((double)l * (l + 1) - mi * (mi + 1.0));
            cr += -0.5 * s * Qre[(k - 1) * d + b];
            ci += -0.5 * s * Qim[(k - 1) * d + b];
        }
        if (k + 1 < d) {
            double mi = (double)(k - l);
            double s = sqrt((double)l * (l + 1) - mi * (mi + 1.0));
            cr += 0.5 * s * Qre[(k + 1) * d + b];
            ci += 0.5 * s * Qim[(k + 1) * d + b];
        }
        Cre[t] = cr; Cim[t] = ci;
    }
    __syncthreads();
    if (t < dd) {
        int a = t / d, b = t % d;
        double x0 = 0.0, x1 = 0.0;
        for (int k = 0; k < d; k++) {
            double ra = Qre[k * d + a], ia = Qim[k * d + a];
            double rb = Qre[k * d + b], ib = Qim[k * d + b];
            double mk = (double)(k - l);
            x1 += -mk * (ra * ib - ia * rb);            // Re(conj(Qka)*(i mk)*Qkb)
            x0 += ra * Cre[k * d + b] + ia * Cim[k * d + b];
        }
        g_X0[l][t] = x0; g_X1[l][t] = x1;
    }
}

// ============ setup: matrix exponentials (scaling & squaring, fp64) ============
__global__ void k_expm() {
    int job = blockIdx.x;
    int l = job / 48, r = job % 48;
    int d = 2 * l + 1, dd = d * d;
    double ang; const double* gen; float* dst;
    if (r < 16)      { ang = 2.0 * PI_D * r / 16.0; gen = g_X1[l]; dst = g_EY[l][r]; }
    else if (r < 24) { ang = g_beta[r - 16];        gen = g_X0[l]; dst = g_EB[l][r - 16]; }
    else if (r < 32) { ang = g_c8a[r - 24];         gen = g_X1[l]; dst = g_RA[l][r - 24]; }
    else if (r < 40) { ang = g_c8b[r - 32];         gen = g_X0[l]; dst = g_RB[l][r - 32]; }
    else             { ang = g_c8g[r - 40];         gen = g_X1[l]; dst = g_RG[l][r - 40]; }
    __shared__ double A[169], E[169], P[169], T[169];
    int t = threadIdx.x;
    double sc = ang / 512.0; // 2^9
    if (t < dd) {
        A[t] = gen[t] * sc;
        double id = (t % (d + 1) == 0) ? 1.0 : 0.0;
        E[t] = id + A[t];
        P[t] = A[t];
    }
    __syncthreads();
    for (int k = 2; k <= 12; k++) {
        if (t < dd) {
            int i = t / d, j = t % d;
            double s = 0.0;
            for (int n = 0; n < d; n++) s += P[i * d + n] * A[n * d + j];
            T[t] = s / (double)k;
        }
        __syncthreads();
        if (t < dd) { P[t] = T[t]; E[t] += T[t]; }
        __syncthreads();
    }
    for (int q = 0; q < 9; q++) {
        if (t < dd) {
            int i = t / d, j = t % d;
            double s = 0.0;
            for (int n = 0; n < d; n++) s += E[i * d + n] * E[n * d + j];
            T[t] = s;
        }
        __syncthreads();
        if (t < dd) E[t] = T[t];
        __syncthreads();
    }
    if (t < dd) dst[t] = (float)E[t];
}

// ============ setup: Fab = EY[ia] @ EB[ib] ============
__global__ void k_fab() {
    int b = blockIdx.x;
    int l = b / 128, idx = b % 128;
    int ia = idx / 8, ib = idx % 8;
    int d = 2 * l + 1, dd = d * d;
    __shared__ float A[169], B[169];
    int t = threadIdx.x;
    if (t < dd) { A[t] = g_EY[l][ia][t]; B[t] = g_EB[l][ib][t]; }
    __syncthreads();
    if (t < dd) {
        int i = t / d, j = t % d;
        float s = 0.f;
        for (int n = 0; n < d; n++) s += A[i * d + n] * B[n * d + j];
        g_Fab[l][idx][t] = s;
    }
}

// ============ setup: D_OUTW (with quadrature) and D_IN ============
__global__ void k_dout() {
    int g = blockIdx.x;
    int ic = g % 16, ib = (g / 16) % 8, ia = g / 128;
    float qw = (float)g_qw[ib];
    __shared__ float F[169], C[169];
    int t = threadIdx.x;
    for (int l = 0; l <= 6; l++) {
        int d = 2 * l + 1, dd = d * d, off = c_OFF[l];
        if (t < dd) { F[t] = g_Fab[l][ia * 8 + ib][t]; C[t] = g_EY[l][ic][t]; }
        __syncthreads();
        if (t < dd) {
            int i = t / d, j = t % d;
            float s = 0.f;
            for (int n = 0; n < d; n++) s += F[i * d + n] * C[n * d + j];
            float sq = sqrtf(2.0f * l + 1.0f);
            g_DOUTW[g][off + t] = s * sq * qw;
            if (l <= 1) g_DIN[g][off + t] = s * sq;
        }
        __syncthreads();
    }
}

// ============ setup: C8W rows ============
__global__ void k_c8() {
    int i8 = blockIdx.x;
    int t = threadIdx.x;
    __shared__ float A[169], B[169], C[169], T[169];
    for (int l = 0; l <= 6; l++) {
        int d = 2 * l + 1, dd = d * d, off = c_OFF[l];
        if (t < dd) { A[t] = g_RA[l][i8][t]; B[t] = g_RB[l][i8][t]; C[t] = g_RG[l][i8][t]; }
        __syncthreads();
        if (t < dd) {
            int i = t / d, j = t % d;
            float s = 0.f;
            for (int n = 0; n < d; n++) s += A[i * d + n] * B[n * d + j];
            T[t] = s;
        }
        __syncthreads();
        if (t < dd) {
            int i = t / d, j = t % d;
            float s = 0.f;
            for (int n = 0; n < d; n++) s += T[i * d + n] * C[n * d + j];
            g_C8W[i8][off + t] = s * sqrtf(2.0f * l + 1.0f);
        }
        __syncthreads();
    }
}

// ============ setup: fused proj_2 + C8 operator M2T[7280][512] ============
__global__ void k_m2(const float* w2_0, const float* w2_1, const float* w2_2,
                     const float* w2_3, const float* w2_4, const float* w2_5,
                     const float* w2_6) {
    int jf = blockIdx.x;      // 0..7279
    int gi = threadIdx.x;     // 0..511
    int f = jf / 455, j = jf % 455;
    int l = 0;
    #pragma unroll
    for (int ll = 1; ll <= 6; ll++) if (j >= c_OFF[ll]) l = ll;
    int d = 2 * l + 1, off = c_OFF[l];
    int u = (j - off) / d, m = (j - off) % d;
    const float* w2 = (l == 0) ? w2_0 : (l == 1) ? w2_1 : (l == 2) ? w2_2 :
                      (l == 3) ? w2_3 : (l == 4) ? w2_4 : (l == 5) ? w2_5 : w2_6;
    int g = gi >> 3, i = gi & 7;
    float s = 0.f;
    for (int w = 0; w < d; w++)
        s += w2[((f * 64 + g) * d + u) * d + w] * g_C8W[i][off + w * d + m];
    g_M2T[jf][gi] = s * (1.0f / sqrtf(16.0f * d));
}

// ============ main: proj_1 -> featin[8192][10] ============
__global__ void k_featin(const float* traj, const float* w1_0, const float* w1_1) {
    int r = blockIdx.x * blockDim.x + threadIdx.x;
    if (r >= 8192) return;
    int bt = r >> 4, f = r & 15;
    const float* tr = traj + bt * 10;
    g_featin[r][0] = tr[9] * w1_0[f];
    const float inv3 = 0.57735026918962576f;
    #pragma unroll
    for (int w = 0; w < 3; w++)
        #pragma unroll
        for (int m = 0; m < 3; m++) {
            float s = 0.f;
            #pragma unroll
            for (int u = 0; u < 3; u++) s += tr[u * 3 + m] * w1_1[(f * 3 + u) * 3 + w];
            g_featin[r][1 + w * 3 + m] = s * inv3;
        }
}

// ============ main: grid synthesis + relu*sqrt2 -> sig[8192][2048] ============
__global__ void k_gemm1() {
    __shared__ float Fs[64][10];
    __shared__ float Ds[128][10];
    int g0 = blockIdx.x * 128, r0 = blockIdx.y * 64;
    int t = threadIdx.x;
    for (int idx = t; idx < 640; idx += 256) Fs[idx / 10][idx % 10] = g_featin[r0 + idx / 10][idx % 10];
    for (int idx = t; idx < 1280; idx += 256) Ds[idx / 10][idx % 10] = g_DIN[g0 + idx / 10][idx % 10];
    __syncthreads();
    int gl = t & 127, half = t >> 7;
    float dv[10];
    #pragma unroll
    for (int i = 0; i < 10; i++) dv[i] = Ds[gl][i];
    #pragma unroll 4
    for (int rr = half * 32; rr < half * 32 + 32; rr++) {
        float s = 0.f;
        #pragma unroll
        for (int i = 0; i < 10; i++) s += Fs[rr][i] * dv[i];
        g_sig[r0 + rr][g0 + gl] = fmaxf(s, 0.0f) * 1.41421356237309515f;
    }
}

// ============ main: GEMM2 feat = sig(8192x2048) @ D_OUTW(2048x455) ============
__global__ void k_gemm2() {
    __shared__ float As[16 * 129]; // As[k][m] padded
    __shared__ float Bs[16 * 64];
    int n0 = blockIdx.x * 64, m0 = blockIdx.y * 128;
    int t = threadIdx.x;
    int tx = t & 15, ty = t >> 4;
    float acc[8][4] = {};
    for (int k0 = 0; k0 < 2048; k0 += 16) {
        #pragma unroll
        for (int j = 0; j < 8; j++) {
            int idx = t + j * 256;
            int kk = idx & 15, mm = idx >> 4;
            As[kk * 129 + mm] = g_sig[m0 + mm][k0 + kk];
        }
        #pragma unroll
        for (int j = 0; j < 4; j++) {
            int idx = t + j * 256;
            int nn = idx & 63, kk = idx >> 6;
            int gn = n0 + nn;
            Bs[kk * 64 + nn] = (gn < 455) ? g_DOUTW[k0 + kk][gn] : 0.0f;
        }
        __syncthreads();
        #pragma unroll
        for (int kk = 0; kk < 16; kk++) {
            float a[8], b[4];
            #pragma unroll
            for (int i = 0; i < 8; i++) a[i] = As[kk * 129 + ty * 8 + i];
            #pragma unroll
            for (int j = 0; j < 4; j++) b[j] = Bs[kk * 64 + tx * 4 + j];
            #pragma unroll
            for (int i = 0; i < 8; i++)
                #pragma unroll
                for (int j = 0; j < 4; j++) acc[i][j] += a[i] * b[j];
        }
        __syncthreads();
    }
    #pragma unroll
    for (int i = 0; i < 8; i++) {
        int gm = m0 + ty * 8 + i;
        #pragma unroll
        for (int j = 0; j < 4; j++) {
            int gn = n0 + tx * 4 + j;
            if (gn < 455) g_feat[gm][gn] = acc[i][j];
        }
    }
}

// ============ main: GEMM3 split-K : feat(512x7280) @ M2T(7280x512) ============
__global__ void k_gemm3() {
    __shared__ float As[16 * 65];
    __shared__ float Bs[16 * 64];
    int n0 = blockIdx.x * 64, m0 = blockIdx.y * 64, sp = blockIdx.z;
    const float* A = &g_feat[0][0];
    int kbeg = sp * 910, kend = (sp == 7) ? 7280 : (sp + 1) * 910;
    int t = threadIdx.x, tx = t & 15, ty = t >> 4;
    float acc[4][4] = {};
    for (int k0 = kbeg; k0 < kend; k0 += 16) {
        #pragma unroll
        for (int j = 0; j < 4; j++) {
            int idx = t + j * 256; int kk = idx & 15, mm = idx >> 4;
            int gk = k0 + kk;
            As[kk * 65 + mm] = (gk < kend) ? A[(m0 + mm) * 7280 + gk] : 0.0f;
        }
        #pragma unroll
        for (int j = 0; j < 4; j++) {
            int idx = t + j * 256; int nn = idx & 63, kk = idx >> 6;
            int gk = k0 + kk;
            Bs[kk * 64 + nn] = (gk < kend) ? g_M2T[gk][n0 + nn] : 0.0f;
        }
        __syncthreads();
        #pragma unroll
        for (int kk = 0; kk < 16; kk++) {
            float a[4], b[4];
            #pragma unroll
            for (int i = 0; i < 4; i++) a[i] = As[kk * 65 + ty * 4 + i];
            #pragma unroll
            for (int j = 0; j < 4; j++) b[j] = Bs[kk * 64 + tx * 4 + j];
            #pragma unroll
            for (int i = 0; i < 4; i++)
                #pragma unroll
                for (int j = 0; j < 4; j++) acc[i][j] += a[i] * b[j];
        }
        __syncthreads();
    }
    #pragma unroll
    for (int i = 0; i < 4; i++)
        #pragma unroll
        for (int j = 0; j < 4; j++)
            g_part[sp][m0 + ty * 4 + i][n0 + tx * 4 + j] = acc[i][j];
}

__global__ void k_reduce(float* out_traj) {
    int idx = blockIdx.x * blockDim.x + threadIdx.x;
    if (idx >= 262144) return;
    int bt = idx >> 9, gi = idx & 511;
    float s = 0.f;
    #pragma unroll
    for (int sp = 0; sp < 8; sp++) s += g_part[sp][bt][gi];
    out_traj[idx] = s;
}

// ============ main: x_c8 = x(65536x455) @ C8W^T ============
__global__ void k_xc8(const float* __restrict__ x, float* __restrict__ out) {
    __shared__ float C[8 * 455];
    int t = threadIdx.x;
    for (int idx = t; idx < 3640; idx += 256) C[idx] = g_C8W[idx / 455][idx % 455];
    __syncthreads();
    int warp = t >> 5, lane = t & 31;
    long long row = (long long)blockIdx.x * 8 + warp;
    const float* xr = x + row * 455;
    float acc[8] = {};
    for (int j = lane; j < 455; j += 32) {
        float v = xr[j];
        #pragma unroll
        for (int i = 0; i < 8; i++) acc[i] += v * C[i * 455 + j];
    }
    #pragma unroll
    for (int i = 0; i < 8; i++)
        #pragma unroll
        for (int o = 16; o > 0; o >>= 1) acc[i] += __shfl_xor_sync(0xffffffffu, acc[i], o);
    if (lane == 0) {
        float* o8 = out + row * 8;
        #pragma unroll
        for (int i = 0; i < 8; i++) o8[i] = acc[i];
    }
}

// ================= launch =================
extern "C" void kernel_launch(void* const* d_in, const int* in_sizes, int n_in,
                              void* d_out, int out_size) {
    const float* x    = (const float*)d_in[0];
    const float* traj = (const float*)d_in[1];
    const float* w1_0 = (const float*)d_in[2];
    const float* w1_1 = (const float*)d_in[3];
    const float* w2_0 = (const float*)d_in[4];
    const float* w2_1 = (const float*)d_in[5];
    const float* w2_2 = (const float*)d_in[6];
    const float* w2_3 = (const float*)d_in[7];
    const float* w2_4 = (const float*)d_in[8];
    const float* w2_5 = (const float*)d_in[9];
    const float* w2_6 = (const float*)d_in[10];
    float* out = (float*)d_out;
    float* out_traj = out + 524288;

    // ---- constant construction (device-side, every launch) ----
    k_init<<<1, 32>>>();
    k_gen<<<7, 192>>>();
    k_expm<<<336, 192>>>();
    k_fab<<<896, 192>>>();
    k_dout<<<2048, 256>>>();
    k_c8<<<8, 192>>>();
    k_m2<<<7280, 512>>>(w2_0, w2_1, w2_2, w2_3, w2_4, w2_5, w2_6);

    // ---- trajectory branch ----
    k_featin<<<32, 256>>>(traj, w1_0, w1_1);
    k_gemm1<<<dim3(16, 128), 256>>>();
    k_gemm2<<<dim3(8, 64), 256>>>();
    k_gemm3<<<dim3(8, 8, 8), 256>>>();
    k_reduce<<<1024, 256>>>(out_traj);

    // ---- x branch ----
    k_xc8<<<8192, 256>>>(x, out);
}

// round 4
// speedup vs baseline: 1.4244x; 1.4244x over previous
#include <cuda_runtime.h>
#include <cuda_bf16.h>

#define PI_D 3.14159265358979323846
#define JP 456   // padded wigner width (455 -> 456, multiple of 8)
#define K3 7296  // 16 * 456

// ---------------- constants / scratch ----------------
__device__ __constant__ int c_OFF[8] = {0,1,10,35,84,165,286,455};

__device__ double g_qw[8], g_beta[8];
__device__ double g_c8a[8], g_c8b[8], g_c8g[8];
__device__ double g_X0[7][169], g_X1[7][169];

__device__ float g_EY[7][16][169];
__device__ float g_EB[7][8][169];
__device__ float g_RA[7][8][169];
__device__ float g_RB[7][8][169];
__device__ float g_RG[7][8][169];
__device__ float g_Fab[7][128][169];

__device__ float g_DIN[2048][10];
__device__ float g_C8W[8][455];

__device__ __nv_bfloat16 g_DWH[2048][512], g_DWL[2048][512];   // D_OUTW split, padded
__device__ __nv_bfloat16 g_M2TH[K3][512],  g_M2TL[K3][512];    // fused proj2+C8, split
__device__ __nv_bfloat16 g_sigH[8192][2048], g_sigL[8192][2048];
__device__ __nv_bfloat16 g_featH[8192][JP],  g_featL[8192][JP];

__device__ float g_featin[8192][10];
__device__ float g_part[4][512][512];

// ---------------- mma helpers ----------------
__device__ __forceinline__ unsigned smem_u32(const void* p) {
    unsigned a;
    asm("{ .reg .u64 t; cvta.to.shared.u64 t, %1; cvt.u32.u64 %0, t; }" : "=r"(a) : "l"(p));
    return a;
}
__device__ __forceinline__ void ldsm_x4(unsigned addr, unsigned& r0, unsigned& r1, unsigned& r2, unsigned& r3) {
    asm volatile("ldmatrix.sync.aligned.m8n8.x4.shared.b16 {%0,%1,%2,%3}, [%4];"
                 : "=r"(r0), "=r"(r1), "=r"(r2), "=r"(r3) : "r"(addr));
}
__device__ __forceinline__ void ldsm_x4_t(unsigned addr, unsigned& r0, unsigned& r1, unsigned& r2, unsigned& r3) {
    asm volatile("ldmatrix.sync.aligned.m8n8.x4.trans.shared.b16 {%0,%1,%2,%3}, [%4];"
                 : "=r"(r0), "=r"(r1), "=r"(r2), "=r"(r3) : "r"(addr));
}
__device__ __forceinline__ void mma16816(float* c, const unsigned* a, unsigned b0, unsigned b1) {
    asm volatile("mma.sync.aligned.m16n8k16.row.col.f32.bf16.bf16.f32 "
                 "{%0,%1,%2,%3}, {%4,%5,%6,%7}, {%8,%9}, {%0,%1,%2,%3};"
                 : "+f"(c[0]), "+f"(c[1]), "+f"(c[2]), "+f"(c[3])
                 : "r"(a[0]), "r"(a[1]), "r"(a[2]), "r"(a[3]), "r"(b0), "r"(b1));
}
__device__ __forceinline__ void bf16split(float v, __nv_bfloat16& h, __nv_bfloat16& l) {
    h = __float2bfloat16(v);
    l = __float2bfloat16(v - __bfloat162float(h));
}

// ================= setup: GL nodes + C8 Euler angles =================
__global__ void k_init() {
    int t = threadIdx.x;
    if (t < 4) {
        double x = cos(PI_D * (t + 0.75) / 8.5);
        double pp = 1.0;
        for (int it = 0; it < 60; it++) {
            double p0 = 1.0, p1 = x;
            for (int k = 2; k <= 8; k++) {
                double p2 = ((2.0 * k - 1.0) * x * p1 - (k - 1.0) * p0) / k;
                p0 = p1; p1 = p2;
            }
            pp = 8.0 * (x * p1 - p0) / (x * x - 1.0);
            x -= p1 / pp;
        }
        double w = 2.0 / ((1.0 - x * x) * pp * pp);
        g_qw[t] = w / 512.0;  g_qw[7 - t] = w / 512.0;
        g_beta[t] = acos(-x); g_beta[7 - t] = acos(x);
    }
    if (t >= 8 && t < 16) {
        int i = t - 8;
        double th = 2.0 * PI_D * i / 8.0;
        double st = sin(th), ct = cos(th);
        double b = acos(fmin(1.0, fmax(-1.0, ct)));
        double a = atan2(st, 0.0);
        double sa = sin(a), ca = cos(a);
        double g = atan2(-sa, ca * ct);
        g_c8a[i] = a; g_c8b[i] = b; g_c8g[i] = g;
    }
}

// ============ setup: real so(3) generators ============
__global__ void k_gen() {
    int l = blockIdx.x;
    int d = 2 * l + 1, dd = d * d;
    __shared__ double Qre[169], Qim[169], Cre[169], Cim[169];
    int t = threadIdx.x;
    if (t < dd) { Qre[t] = 0.0; Qim[t] = 0.0; }
    __syncthreads();
    if (t == 0) {
        const double r2 = 0.7071067811865475244;
        for (int m = -l; m < 0; m++) {
            Qre[(l + m) * d + (l - m)] = r2;
            Qim[(l + m) * d + (l + m)] = -r2;
        }
        Qre[l * d + l] = 1.0;
        for (int m = 1; m <= l; m++) {
            double s = (m & 1) ? -1.0 : 1.0;
            Qre[(l + m) * d + (l + m)] = s * r2;
            Qim[(l + m) * d + (l - m)] = s * r2;
        }
    }
    __syncthreads();
    if (t < dd) {
        double re = Qre[t], im = Qim[t];
        switch (l & 3) {
            case 1: Qre[t] = im;  Qim[t] = -re; break;
            case 2: Qre[t] = -re; Qim[t] = -im; break;
            case 3: Qre[t] = -im; Qim[t] = re;  break;
            default: break;
        }
    }
    __syncthreads();
    if (t < dd) {
        int k = t / d, b = t % d;
        double cr = 0.0, ci = 0.0;
        if (k >= 1) {
            double mi = (double)(k - 1 - l);
            double s = sqrt((double)l * (l + 1) - mi * (mi + 1.0));
            cr += -0.5 * s * Qre[(k - 1) * d + b];
            ci += -0.5 * s * Qim[(k - 1) * d + b];
        }
        if (k + 1 < d) {
            double mi = (double)(k - l);
            double s = sqrt((double)l * (l + 1) - mi * (mi + 1.0));
            cr += 0.5 * s * Qre[(k + 1) * d + b];
            ci += 0.5 * s * Qim[(k + 1) * d + b];
        }
        Cre[t] = cr; Cim[t] = ci;
    }
    __syncthreads();
    if (t < dd) {
        int a = t / d, b = t % d;
        double x0 = 0.0, x1 = 0.0;
        for (int k = 0; k < d; k++) {
            double ra = Qre[k * d + a], ia = Qim[k * d + a];
            double rb = Qre[k * d + b], ib = Qim[k * d + b];
            double mk = (double)(k - l);
            x1 += -mk * (ra * ib - ia * rb);
            x0 += ra * Cre[k * d + b] + ia * Cim[k * d + b];
        }
        g_X0[l][t] = x0; g_X1[l][t] = x1;
    }
}

// ============ setup: matrix exponentials ============
__global__ void k_expm() {
    int job = blockIdx.x;
    int l = job / 48, r = job % 48;
    int d = 2 * l + 1, dd = d * d;
    double ang; const double* gen; float* dst;
    if (r < 16)      { ang = 2.0 * PI_D * r / 16.0; gen = g_X1[l]; dst = g_EY[l][r]; }
    else if (r < 24) { ang = g_beta[r - 16];        gen = g_X0[l]; dst = g_EB[l][r - 16]; }
    else if (r < 32) { ang = g_c8a[r - 24];         gen = g_X1[l]; dst = g_RA[l][r - 24]; }
    else if (r < 40) { ang = g_c8b[r - 32];         gen = g_X0[l]; dst = g_RB[l][r - 32]; }
    else             { ang = g_c8g[r - 40];         gen = g_X1[l]; dst = g_RG[l][r - 40]; }
    __shared__ double A[169], E[169], P[169], T[169];
    int t = threadIdx.x;
    double sc = ang / 512.0;
    if (t < dd) {
        A[t] = gen[t] * sc;
        double id = (t % (d + 1) == 0) ? 1.0 : 0.0;
        E[t] = id + A[t];
        P[t] = A[t];
    }
    __syncthreads();
    for (int k = 2; k <= 12; k++) {
        if (t < dd) {
            int i = t / d, j = t % d;
            double s = 0.0;
            for (int n = 0; n < d; n++) s += P[i * d + n] * A[n * d + j];
            T[t] = s / (double)k;
        }
        __syncthreads();
        if (t < dd) { P[t] = T[t]; E[t] += T[t]; }
        __syncthreads();
    }
    for (int q = 0; q < 9; q++) {
        if (t < dd) {
            int i = t / d, j = t % d;
            double s = 0.0;
            for (int n = 0; n < d; n++) s += E[i * d + n] * E[n * d + j];
            T[t] = s;
        }
        __syncthreads();
        if (t < dd) E[t] = T[t];
        __syncthreads();
    }
    if (t < dd) dst[t] = (float)E[t];
}

// ============ setup: Fab = EY[ia] @ EB[ib] ============
__global__ void k_fab() {
    int b = blockIdx.x;
    int l = b / 128, idx = b % 128;
    int ia = idx / 8, ib = idx % 8;
    int d = 2 * l + 1, dd = d * d;
    __shared__ float A[169], B[169];
    int t = threadIdx.x;
    if (t < dd) { A[t] = g_EY[l][ia][t]; B[t] = g_EB[l][ib][t]; }
    __syncthreads();
    if (t < dd) {
        int i = t / d, j = t % d;
        float s = 0.f;
        for (int n = 0; n < d; n++) s += A[i * d + n] * B[n * d + j];
        g_Fab[l][idx][t] = s;
    }
}

// ============ setup: D_OUTW (bf16 split, padded) and D_IN ============
__global__ void k_dout() {
    int g = blockIdx.x;
    int ic = g % 16, ib = (g / 16) % 8, ia = g / 128;
    float qw = (float)g_qw[ib];
    __shared__ float F[169], C[169];
    int t = threadIdx.x;
    if (t < 57) {  // zero pad cols 455..511
        g_DWH[g][455 + t] = __float2bfloat16(0.f);
        g_DWL[g][455 + t] = __float2bfloat16(0.f);
    }
    for (int l = 0; l <= 6; l++) {
        int d = 2 * l + 1, dd = d * d, off = c_OFF[l];
        if (t < dd) { F[t] = g_Fab[l][ia * 8 + ib][t]; C[t] = g_EY[l][ic][t]; }
        __syncthreads();
        if (t < dd) {
            int i = t / d, j = t % d;
            float s = 0.f;
            for (int n = 0; n < d; n++) s += F[i * d + n] * C[n * d + j];
            float sq = sqrtf(2.0f * l + 1.0f);
            float v = s * sq * qw;
            __nv_bfloat16 h, lo; bf16split(v, h, lo);
            g_DWH[g][off + t] = h; g_DWL[g][off + t] = lo;
            if (l <= 1) g_DIN[g][off + t] = s * sq;
        }
        __syncthreads();
    }
}

// ============ setup: C8W rows ============
__global__ void k_c8() {
    int i8 = blockIdx.x;
    int t = threadIdx.x;
    __shared__ float A[169], B[169], C[169], T[169];
    for (int l = 0; l <= 6; l++) {
        int d = 2 * l + 1, dd = d * d, off = c_OFF[l];
        if (t < dd) { A[t] = g_RA[l][i8][t]; B[t] = g_RB[l][i8][t]; C[t] = g_RG[l][i8][t]; }
        __syncthreads();
        if (t < dd) {
            int i = t / d, j = t % d;
            float s = 0.f;
            for (int n = 0; n < d; n++) s += A[i * d + n] * B[n * d + j];
            T[t] = s;
        }
        __syncthreads();
        if (t < dd) {
            int i = t / d, j = t % d;
            float s = 0.f;
            for (int n = 0; n < d; n++) s += T[i * d + n] * C[n * d + j];
            g_C8W[i8][off + t] = s * sqrtf(2.0f * l + 1.0f);
        }
        __syncthreads();
    }
}

// ============ setup: fused proj_2 + C8 operator (bf16 split, K-padded) ============
__global__ void k_m2(const float* w2_0, const float* w2_1, const float* w2_2,
                     const float* w2_3, const float* w2_4, const float* w2_5,
                     const float* w2_6) {
    int jf = blockIdx.x;      // 0..K3-1
    int gi = threadIdx.x;     // 0..511
    int f = jf / JP, j = jf % JP;
    if (j == 455) {  // pad row
        g_M2TH[jf][gi] = __float2bfloat16(0.f);
        g_M2TL[jf][gi] = __float2bfloat16(0.f);
        return;
    }
    int l = 0;
    #pragma unroll
    for (int ll = 1; ll <= 6; ll++) if (j >= c_OFF[ll]) l = ll;
    int d = 2 * l + 1, off = c_OFF[l];
    int u = (j - off) / d, m = (j - off) % d;
    const float* w2 = (l == 0) ? w2_0 : (l == 1) ? w2_1 : (l == 2) ? w2_2 :
                      (l == 3) ? w2_3 : (l == 4) ? w2_4 : (l == 5) ? w2_5 : w2_6;
    int g = gi >> 3, i = gi & 7;
    float s = 0.f;
    for (int w = 0; w < d; w++)
        s += w2[((f * 64 + g) * d + u) * d + w] * g_C8W[i][off + w * d + m];
    s *= (1.0f / sqrtf(16.0f * d));
    __nv_bfloat16 h, lo; bf16split(s, h, lo);
    g_M2TH[jf][gi] = h; g_M2TL[jf][gi] = lo;
}

// ============ main: proj_1 ============
__global__ void k_featin(const float* traj, const float* w1_0, const float* w1_1) {
    int r = blockIdx.x * blockDim.x + threadIdx.x;
    if (r >= 8192) return;
    int bt = r >> 4, f = r & 15;
    const float* tr = traj + bt * 10;
    g_featin[r][0] = tr[9] * w1_0[f];
    const float inv3 = 0.57735026918962576f;
    #pragma unroll
    for (int w = 0; w < 3; w++)
        #pragma unroll
        for (int m = 0; m < 3; m++) {
            float s = 0.f;
            #pragma unroll
            for (int u = 0; u < 3; u++) s += tr[u * 3 + m] * w1_1[(f * 3 + u) * 3 + w];
            g_featin[r][1 + w * 3 + m] = s * inv3;
        }
}

// ============ main: grid synthesis + relu*sqrt2 -> sig (bf16 split) ============
__global__ void k_gemm1() {
    __shared__ float Fs[64][10];
    __shared__ float Ds[128][10];
    int g0 = blockIdx.x * 128, r0 = blockIdx.y * 64;
    int t = threadIdx.x;
    for (int idx = t; idx < 640; idx += 256) Fs[idx / 10][idx % 10] = g_featin[r0 + idx / 10][idx % 10];
    for (int idx = t; idx < 1280; idx += 256) Ds[idx / 10][idx % 10] = g_DIN[g0 + idx / 10][idx % 10];
    __syncthreads();
    int gl = t & 127, half = t >> 7;
    float dv[10];
    #pragma unroll
    for (int i = 0; i < 10; i++) dv[i] = Ds[gl][i];
    #pragma unroll 4
    for (int rr = half * 32; rr < half * 32 + 32; rr++) {
        float s = 0.f;
        #pragma unroll
        for (int i = 0; i < 10; i++) s += Fs[rr][i] * dv[i];
        s = fmaxf(s, 0.0f) * 1.41421356237309515f;
        __nv_bfloat16 h, lo; bf16split(s, h, lo);
        g_sigH[r0 + rr][g0 + gl] = h;
        g_sigL[r0 + rr][g0 + gl] = lo;
    }
}

// ============ main: GEMM2 (tensor) feat = sig @ D_OUTW ============
__global__ __launch_bounds__(256) void k_gemm2t() {
    __shared__ __align__(16) __nv_bfloat16 As[2][128][40];
    __shared__ __align__(16) __nv_bfloat16 Bs[2][32][72];
    int m0 = blockIdx.y * 128, n0 = blockIdx.x * 64;
    int t = threadIdx.x, lane = t & 31, wid = t >> 5;
    int wm = (wid & 3) * 32, wn = (wid >> 2) * 32;
    float acc[2][4][4] = {};
    unsigned aB = smem_u32(&As[0][0][0]);
    unsigned bB = smem_u32(&Bs[0][0][0]);

    for (int k0 = 0; k0 < 2048; k0 += 32) {
        #pragma unroll
        for (int v = 0; v < 2; v++) {
            int idx = t + v * 256;
            int r = idx >> 2, c8 = (idx & 3) * 8;
            *(uint4*)&As[0][r][c8] = *(const uint4*)&g_sigH[m0 + r][k0 + c8];
            *(uint4*)&As[1][r][c8] = *(const uint4*)&g_sigL[m0 + r][k0 + c8];
        }
        {
            int r = t >> 3, c8 = (t & 7) * 8;   // 256 threads: full 32x64 tile
            *(uint4*)&Bs[0][r][c8] = *(const uint4*)&g_DWH[k0 + r][n0 + c8];
            *(uint4*)&Bs[1][r][c8] = *(const uint4*)&g_DWL[k0 + r][n0 + c8];
        }
        __syncthreads();
        #pragma unroll
        for (int ks = 0; ks < 2; ks++) {
            unsigned ah[2][4], al[2][4], bh[2][4], bl[2][4];
            #pragma unroll
            for (int mt = 0; mt < 2; mt++) {
                unsigned off = ((wm + mt * 16 + (lane & 15)) * 40 + ks * 16 + ((lane >> 4) * 8)) * 2;
                ldsm_x4(aB + off, ah[mt][0], ah[mt][1], ah[mt][2], ah[mt][3]);
                ldsm_x4(aB + off + 128 * 40 * 2, al[mt][0], al[mt][1], al[mt][2], al[mt][3]);
            }
            #pragma unroll
            for (int p = 0; p < 2; p++) {
                unsigned off = ((ks * 16 + (lane & 15)) * 72 + wn + p * 16 + ((lane >> 4) * 8)) * 2;
                ldsm_x4_t(bB + off, bh[p][0], bh[p][1], bh[p][2], bh[p][3]);
                ldsm_x4_t(bB + off + 32 * 72 * 2, bl[p][0], bl[p][1], bl[p][2], bl[p][3]);
            }
            #pragma unroll
            for (int mt = 0; mt < 2; mt++)
                #pragma unroll
                for (int nt = 0; nt < 4; nt++) {
                    int p = nt >> 1, q = (nt & 1) * 2;
                    mma16816(acc[mt][nt], ah[mt], bh[p][q], bh[p][q + 1]);
                    mma16816(acc[mt][nt], al[mt], bh[p][q], bh[p][q + 1]);
                    mma16816(acc[mt][nt], ah[mt], bl[p][q], bl[p][q + 1]);
                }
        }
        __syncthreads();
    }
    int rr = lane >> 2, cc = (lane & 3) * 2;
    #pragma unroll
    for (int mt = 0; mt < 2; mt++)
        #pragma unroll
        for (int nt = 0; nt < 4; nt++) {
            int grow = m0 + wm + mt * 16 + rr;
            int gcol = n0 + wn + nt * 8 + cc;
            if (gcol < JP) {
                __nv_bfloat16 h, lo;
                bf16split(acc[mt][nt][0], h, lo); g_featH[grow][gcol] = h;     g_featL[grow][gcol] = lo;
                bf16split(acc[mt][nt][1], h, lo); g_featH[grow][gcol + 1] = h; g_featL[grow][gcol + 1] = lo;
                bf16split(acc[mt][nt][2], h, lo); g_featH[grow + 8][gcol] = h;     g_featL[grow + 8][gcol] = lo;
                bf16split(acc[mt][nt][3], h, lo); g_featH[grow + 8][gcol + 1] = h; g_featL[grow + 8][gcol + 1] = lo;
            }
        }
}

// ============ main: GEMM3 (tensor, split-K) out = feat_flat @ M2T ============
__global__ __launch_bounds__(256) void k_gemm3t() {
    __shared__ __align__(16) __nv_bfloat16 As[2][128][40];
    __shared__ __align__(16) __nv_bfloat16 Bs[2][32][72];
    int m0 = blockIdx.y * 128, n0 = blockIdx.x * 64, sp = blockIdx.z;
    int kbeg = sp * 1824;
    int t = threadIdx.x, lane = t & 31, wid = t >> 5;
    int wm = (wid & 3) * 32, wn = (wid >> 2) * 32;
    float acc[2][4][4] = {};
    unsigned aB = smem_u32(&As[0][0][0]);
    unsigned bB = smem_u32(&Bs[0][0][0]);

    for (int k0 = kbeg; k0 < kbeg + 1824; k0 += 32) {
        #pragma unroll
        for (int v = 0; v < 2; v++) {
            int idx = t + v * 256;
            int r = idx >> 2, c8 = (idx & 3) * 8;
            int kk = k0 + c8;
            int f = kk / JP, j = kk - f * JP;
            int frow = (m0 + r) * 16 + f;
            *(uint4*)&As[0][r][c8] = *(const uint4*)&g_featH[frow][j];
            *(uint4*)&As[1][r][c8] = *(const uint4*)&g_featL[frow][j];
        }
        {
            int r = t >> 3, c8 = (t & 7) * 8;   // 256 threads: full 32x64 tile
            *(uint4*)&Bs[0][r][c8] = *(const uint4*)&g_M2TH[k0 + r][n0 + c8];
            *(uint4*)&Bs[1][r][c8] = *(const uint4*)&g_M2TL[k0 + r][n0 + c8];
        }
        __syncthreads();
        #pragma unroll
        for (int ks = 0; ks < 2; ks++) {
            unsigned ah[2][4], al[2][4], bh[2][4], bl[2][4];
            #pragma unroll
            for (int mt = 0; mt < 2; mt++) {
                unsigned off = ((wm + mt * 16 + (lane & 15)) * 40 + ks * 16 + ((lane >> 4) * 8)) * 2;
                ldsm_x4(aB + off, ah[mt][0], ah[mt][1], ah[mt][2], ah[mt][3]);
                ldsm_x4(aB + off + 128 * 40 * 2, al[mt][0], al[mt][1], al[mt][2], al[mt][3]);
            }
            #pragma unroll
            for (int p = 0; p < 2; p++) {
                unsigned off = ((ks * 16 + (lane & 15)) * 72 + wn + p * 16 + ((lane >> 4) * 8)) * 2;
                ldsm_x4_t(bB + off, bh[p][0], bh[p][1], bh[p][2], bh[p][3]);
                ldsm_x4_t(bB + off + 32 * 72 * 2, bl[p][0], bl[p][1], bl[p][2], bl[p][3]);
            }
            #pragma unroll
            for (int mt = 0; mt < 2; mt++)
                #pragma unroll
                for (int nt = 0; nt < 4; nt++) {
                    int p = nt >> 1, q = (nt & 1) * 2;
                    mma16816(acc[mt][nt], ah[mt], bh[p][q], bh[p][q + 1]);
                    mma16816(acc[mt][nt], al[mt], bh[p][q], bh[p][q + 1]);
                    mma16816(acc[mt][nt], ah[mt], bl[p][q], bl[p][q + 1]);
                }
        }
        __syncthreads();
    }
    int rr = lane >> 2, cc = (lane & 3) * 2;
    #pragma unroll
    for (int mt = 0; mt < 2; mt++)
        #pragma unroll
        for (int nt = 0; nt < 4; nt++) {
            int grow = m0 + wm + mt * 16 + rr;
            int gcol = n0 + wn + nt * 8 + cc;
            g_part[sp][grow][gcol]     = acc[mt][nt][0];
            g_part[sp][grow][gcol + 1] = acc[mt][nt][1];
            g_part[sp][grow + 8][gcol]     = acc[mt][nt][2];
            g_part[sp][grow + 8][gcol + 1] = acc[mt][nt][3];
        }
}

__global__ void k_reduce(float* out_traj) {
    int idx = blockIdx.x * blockDim.x + threadIdx.x;
    if (idx >= 262144) return;
    int bt = idx >> 9, gi = idx & 511;
    float s = 0.f;
    #pragma unroll
    for (int sp = 0; sp < 4; sp++) s += g_part[sp][bt][gi];
    out_traj[idx] = s;
}

// ============ main: x_c8 = x @ C8W^T ============
__global__ void k_xc8(const float* __restrict__ x, float* __restrict__ out) {
    __shared__ float C[8 * 455];
    int t = threadIdx.x;
    for (int idx = t; idx < 3640; idx += 256) C[idx] = g_C8W[idx / 455][idx % 455];
    __syncthreads();
    int warp = t >> 5, lane = t & 31;
    long long row = (long long)blockIdx.x * 8 + warp;
    const float* xr = x + row * 455;
    float acc[8] = {};
    for (int j = lane; j < 455; j += 32) {
        float v = xr[j];
        #pragma unroll
        for (int i = 0; i < 8; i++) acc[i] += v * C[i * 455 + j];
    }
    #pragma unroll
    for (int i = 0; i < 8; i++)
        #pragma unroll
        for (int o = 16; o > 0; o >>= 1) acc[i] += __shfl_xor_sync(0xffffffffu, acc[i], o);
    if (lane == 0) {
        float* o8 = out + row * 8;
        #pragma unroll
        for (int i = 0; i < 8; i++) o8[i] = acc[i];
    }
}

// ================= launch =================
extern "C" void kernel_launch(void* const* d_in, const int* in_sizes, int n_in,
                              void* d_out, int out_size) {
    const float* x    = (const float*)d_in[0];
    const float* traj = (const float*)d_in[1];
    const float* w1_0 = (const float*)d_in[2];
    const float* w1_1 = (const float*)d_in[3];
    const float* w2_0 = (const float*)d_in[4];
    const float* w2_1 = (const float*)d_in[5];
    const float* w2_2 = (const float*)d_in[6];
    const float* w2_3 = (const float*)d_in[7];
    const float* w2_4 = (const float*)d_in[8];
    const float* w2_5 = (const float*)d_in[9];
    const float* w2_6 = (const float*)d_in[10];
    float* out = (float*)d_out;
    float* out_traj = out + 524288;

    k_init<<<1, 32>>>();
    k_gen<<<7, 192>>>();
    k_expm<<<336, 192>>>();
    k_fab<<<896, 192>>>();
    k_dout<<<2048, 256>>>();
    k_c8<<<8, 192>>>();
    k_m2<<<K3, 512>>>(w2_0, w2_1, w2_2, w2_3, w2_4, w2_5, w2_6);

    k_featin<<<32, 256>>>(traj, w1_0, w1_1);
    k_gemm1<<<dim3(16, 128), 256>>>();
    k_gemm2t<<<dim3(8, 64), 256>>>();
    k_gemm3t<<<dim3(8, 4, 4), 256>>>();
    k_reduce<<<1024, 256>>>(out_traj);

    k_xc8<<<8192, 256>>>(x, out);
}

// round 5
// speedup vs baseline: 1.5891x; 1.1156x over previous
#include <cuda_runtime.h>
#include <cuda_bf16.h>

#define PI_D 3.14159265358979323846
#define JP 456   // padded wigner width (455 -> 456, multiple of 8)
#define K3 7296  // 16 * 456

// ---------------- constants / scratch ----------------
__device__ __constant__ int c_OFF[8] = {0,1,10,35,84,165,286,455};

__device__ double g_qw[8], g_beta[8];
__device__ double g_c8a[8], g_c8b[8], g_c8g[8];
__device__ double g_X0[7][169], g_X1[7][169];

__device__ float g_EY[7][16][169];
__device__ float g_EB[7][8][169];
__device__ float g_RA[7][8][169];
__device__ float g_RB[7][8][169];
__device__ float g_RG[7][8][169];
__device__ float g_Fab[7][128][169];

__device__ float g_DIN[2048][10];
__device__ float g_C8W[8][455];

__device__ __nv_bfloat16 g_DWH[2048][512], g_DWL[2048][512];   // D_OUTW split, padded
__device__ __nv_bfloat16 g_M2TH[K3][512],  g_M2TL[K3][512];    // fused proj2+C8, split
__device__ __nv_bfloat16 g_sigH[8192][2048], g_sigL[8192][2048];
__device__ __nv_bfloat16 g_featH[8192][JP],  g_featL[8192][JP];

__device__ float g_featin[8192][10];
__device__ float g_part[4][512][512];

// ---------------- mma / async helpers ----------------
__device__ __forceinline__ unsigned smem_u32(const void* p) {
    unsigned a;
    asm("{ .reg .u64 t; cvta.to.shared.u64 t, %1; cvt.u32.u64 %0, t; }" : "=r"(a) : "l"(p));
    return a;
}
__device__ __forceinline__ void ldsm_x4(unsigned addr, unsigned& r0, unsigned& r1, unsigned& r2, unsigned& r3) {
    asm volatile("ldmatrix.sync.aligned.m8n8.x4.shared.b16 {%0,%1,%2,%3}, [%4];"
                 : "=r"(r0), "=r"(r1), "=r"(r2), "=r"(r3) : "r"(addr));
}
__device__ __forceinline__ void ldsm_x4_t(unsigned addr, unsigned& r0, unsigned& r1, unsigned& r2, unsigned& r3) {
    asm volatile("ldmatrix.sync.aligned.m8n8.x4.trans.shared.b16 {%0,%1,%2,%3}, [%4];"
                 : "=r"(r0), "=r"(r1), "=r"(r2), "=r"(r3) : "r"(addr));
}
__device__ __forceinline__ void mma16816(float* c, const unsigned* a, unsigned b0, unsigned b1) {
    asm volatile("mma.sync.aligned.m16n8k16.row.col.f32.bf16.bf16.f32 "
                 "{%0,%1,%2,%3}, {%4,%5,%6,%7}, {%8,%9}, {%0,%1,%2,%3};"
                 : "+f"(c[0]), "+f"(c[1]), "+f"(c[2]), "+f"(c[3])
                 : "r"(a[0]), "r"(a[1]), "r"(a[2]), "r"(a[3]), "r"(b0), "r"(b1));
}
__device__ __forceinline__ void cp16(unsigned dst, const void* src) {
    asm volatile("cp.async.cg.shared.global [%0], [%1], 16;" :: "r"(dst), "l"(src));
}
#define CP_COMMIT asm volatile("cp.async.commit_group;" ::: "memory")
#define CP_WAIT1  asm volatile("cp.async.wait_group 1;" ::: "memory")
__device__ __forceinline__ void bf16split(float v, __nv_bfloat16& h, __nv_bfloat16& l) {
    h = __float2bfloat16(v);
    l = __float2bfloat16(v - __bfloat162float(h));
}

// ================= setup: GL nodes + C8 Euler angles =================
__global__ void k_init() {
    int t = threadIdx.x;
    if (t < 4) {
        double x = cos(PI_D * (t + 0.75) / 8.5);
        double pp = 1.0;
        for (int it = 0; it < 60; it++) {
            double p0 = 1.0, p1 = x;
            for (int k = 2; k <= 8; k++) {
                double p2 = ((2.0 * k - 1.0) * x * p1 - (k - 1.0) * p0) / k;
                p0 = p1; p1 = p2;
            }
            pp = 8.0 * (x * p1 - p0) / (x * x - 1.0);
            x -= p1 / pp;
        }
        double w = 2.0 / ((1.0 - x * x) * pp * pp);
        g_qw[t] = w / 512.0;  g_qw[7 - t] = w / 512.0;
        g_beta[t] = acos(-x); g_beta[7 - t] = acos(x);
    }
    if (t >= 8 && t < 16) {
        int i = t - 8;
        double th = 2.0 * PI_D * i / 8.0;
        double st = sin(th), ct = cos(th);
        double b = acos(fmin(1.0, fmax(-1.0, ct)));
        double a = atan2(st, 0.0);
        double sa = sin(a), ca = cos(a);
        double g = atan2(-sa, ca * ct);
        g_c8a[i] = a; g_c8b[i] = b; g_c8g[i] = g;
    }
}

// ============ setup: real so(3) generators ============
__global__ void k_gen() {
    int l = blockIdx.x;
    int d = 2 * l + 1, dd = d * d;
    __shared__ double Qre[169], Qim[169], Cre[169], Cim[169];
    int t = threadIdx.x;
    if (t < dd) { Qre[t] = 0.0; Qim[t] = 0.0; }
    __syncthreads();
    if (t == 0) {
        const double r2 = 0.7071067811865475244;
        for (int m = -l; m < 0; m++) {
            Qre[(l + m) * d + (l - m)] = r2;
            Qim[(l + m) * d + (l + m)] = -r2;
        }
        Qre[l * d + l] = 1.0;
        for (int m = 1; m <= l; m++) {
            double s = (m & 1) ? -1.0 : 1.0;
            Qre[(l + m) * d + (l + m)] = s * r2;
            Qim[(l + m) * d + (l - m)] = s * r2;
        }
    }
    __syncthreads();
    if (t < dd) {
        double re = Qre[t], im = Qim[t];
        switch (l & 3) {
            case 1: Qre[t] = im;  Qim[t] = -re; break;
            case 2: Qre[t] = -re; Qim[t] = -im; break;
            case 3: Qre[t] = -im; Qim[t] = re;  break;
            default: break;
        }
    }
    __syncthreads();
    if (t < dd) {
        int k = t / d, b = t % d;
        double cr = 0.0, ci = 0.0;
        if (k >= 1) {
            double mi = (double)(k - 1 - l);
            double s = sqrt((double)l * (l + 1) - mi * (mi + 1.0));
            cr += -0.5 * s * Qre[(k - 1) * d + b];
            ci += -0.5 * s * Qim[(k - 1) * d + b];
        }
        if (k + 1 < d) {
            double mi = (double)(k - l);
            double s = sqrt((double)l * (l + 1) - mi * (mi + 1.0));
            cr += 0.5 * s * Qre[(k + 1) * d + b];
            ci += 0.5 * s * Qim[(k + 1) * d + b];
        }
        Cre[t] = cr; Cim[t] = ci;
    }
    __syncthreads();
    if (t < dd) {
        int a = t / d, b = t % d;
        double x0 = 0.0, x1 = 0.0;
        for (int k = 0; k < d; k++) {
            double ra = Qre[k * d + a], ia = Qim[k * d + a];
            double rb = Qre[k * d + b], ib = Qim[k * d + b];
            double mk = (double)(k - l);
            x1 += -mk * (ra * ib - ia * rb);
            x0 += ra * Cre[k * d + b] + ia * Cim[k * d + b];
        }
        g_X0[l][t] = x0; g_X1[l][t] = x1;
    }
}

// ============ setup: matrix exponentials ============
__global__ void k_expm() {
    int job = blockIdx.x;
    int l = job / 48, r = job % 48;
    int d = 2 * l + 1, dd = d * d;
    double ang; const double* gen; float* dst;
    if (r < 16)      { ang = 2.0 * PI_D * r / 16.0; gen = g_X1[l]; dst = g_EY[l][r]; }
    else if (r < 24) { ang = g_beta[r - 16];        gen = g_X0[l]; dst = g_EB[l][r - 16]; }
    else if (r < 32) { ang = g_c8a[r - 24];         gen = g_X1[l]; dst = g_RA[l][r - 24]; }
    else if (r < 40) { ang = g_c8b[r - 32];         gen = g_X0[l]; dst = g_RB[l][r - 32]; }
    else             { ang = g_c8g[r - 40];         gen = g_X1[l]; dst = g_RG[l][r - 40]; }
    __shared__ double A[169], E[169], P[169], T[169];
    int t = threadIdx.x;
    double sc = ang / 512.0;
    if (t < dd) {
        A[t] = gen[t] * sc;
        double id = (t % (d + 1) == 0) ? 1.0 : 0.0;
        E[t] = id + A[t];
        P[t] = A[t];
    }
    __syncthreads();
    for (int k = 2; k <= 12; k++) {
        if (t < dd) {
            int i = t / d, j = t % d;
            double s = 0.0;
            for (int n = 0; n < d; n++) s += P[i * d + n] * A[n * d + j];
            T[t] = s / (double)k;
        }
        __syncthreads();
        if (t < dd) { P[t] = T[t]; E[t] += T[t]; }
        __syncthreads();
    }
    for (int q = 0; q < 9; q++) {
        if (t < dd) {
            int i = t / d, j = t % d;
            double s = 0.0;
            for (int n = 0; n < d; n++) s += E[i * d + n] * E[n * d + j];
            T[t] = s;
        }
        __syncthreads();
        if (t < dd) E[t] = T[t];
        __syncthreads();
    }
    if (t < dd) dst[t] = (float)E[t];
}

// ============ setup: Fab = EY[ia] @ EB[ib] ============
__global__ void k_fab() {
    int b = blockIdx.x;
    int l = b / 128, idx = b % 128;
    int ia = idx / 8, ib = idx % 8;
    int d = 2 * l + 1, dd = d * d;
    __shared__ float A[169], B[169];
    int t = threadIdx.x;
    if (t < dd) { A[t] = g_EY[l][ia][t]; B[t] = g_EB[l][ib][t]; }
    __syncthreads();
    if (t < dd) {
        int i = t / d, j = t % d;
        float s = 0.f;
        for (int n = 0; n < d; n++) s += A[i * d + n] * B[n * d + j];
        g_Fab[l][idx][t] = s;
    }
}

// ============ setup: D_OUTW (bf16 split, padded) and D_IN ============
__global__ void k_dout() {
    int g = blockIdx.x;
    int ic = g % 16, ib = (g / 16) % 8, ia = g / 128;
    float qw = (float)g_qw[ib];
    __shared__ float F[169], C[169];
    int t = threadIdx.x;
    if (t < 57) {  // zero pad cols 455..511
        g_DWH[g][455 + t] = __float2bfloat16(0.f);
        g_DWL[g][455 + t] = __float2bfloat16(0.f);
    }
    for (int l = 0; l <= 6; l++) {
        int d = 2 * l + 1, dd = d * d, off = c_OFF[l];
        if (t < dd) { F[t] = g_Fab[l][ia * 8 + ib][t]; C[t] = g_EY[l][ic][t]; }
        __syncthreads();
        if (t < dd) {
            int i = t / d, j = t % d;
            float s = 0.f;
            for (int n = 0; n < d; n++) s += F[i * d + n] * C[n * d + j];
            float sq = sqrtf(2.0f * l + 1.0f);
            float v = s * sq * qw;
            __nv_bfloat16 h, lo; bf16split(v, h, lo);
            g_DWH[g][off + t] = h; g_DWL[g][off + t] = lo;
            if (l <= 1) g_DIN[g][off + t] = s * sq;
        }
        __syncthreads();
    }
}

// ============ setup: C8W rows ============
__global__ void k_c8() {
    int i8 = blockIdx.x;
    int t = threadIdx.x;
    __shared__ float A[169], B[169], C[169], T[169];
    for (int l = 0; l <= 6; l++) {
        int d = 2 * l + 1, dd = d * d, off = c_OFF[l];
        if (t < dd) { A[t] = g_RA[l][i8][t]; B[t] = g_RB[l][i8][t]; C[t] = g_RG[l][i8][t]; }
        __syncthreads();
        if (t < dd) {
            int i = t / d, j = t % d;
            float s = 0.f;
            for (int n = 0; n < d; n++) s += A[i * d + n] * B[n * d + j];
            T[t] = s;
        }
        __syncthreads();
        if (t < dd) {
            int i = t / d, j = t % d;
            float s = 0.f;
            for (int n = 0; n < d; n++) s += T[i * d + n] * C[n * d + j];
            g_C8W[i8][off + t] = s * sqrtf(2.0f * l + 1.0f);
        }
        __syncthreads();
    }
}

// ============ setup: fused proj_2 + C8 operator (bf16 split, K-padded) ============
__global__ void k_m2(const float* w2_0, const float* w2_1, const float* w2_2,
                     const float* w2_3, const float* w2_4, const float* w2_5,
                     const float* w2_6) {
    int jf = blockIdx.x;      // 0..K3-1
    int gi = threadIdx.x;     // 0..511
    int f = jf / JP, j = jf % JP;
    if (j == 455) {  // pad row
        g_M2TH[jf][gi] = __float2bfloat16(0.f);
        g_M2TL[jf][gi] = __float2bfloat16(0.f);
        return;
    }
    int l = 0;
    #pragma unroll
    for (int ll = 1; ll <= 6; ll++) if (j >= c_OFF[ll]) l = ll;
    int d = 2 * l + 1, off = c_OFF[l];
    int u = (j - off) / d, m = (j - off) % d;
    const float* w2 = (l == 0) ? w2_0 : (l == 1) ? w2_1 : (l == 2) ? w2_2 :
                      (l == 3) ? w2_3 : (l == 4) ? w2_4 : (l == 5) ? w2_5 : w2_6;
    int g = gi >> 3, i = gi & 7;
    float s = 0.f;
    for (int w = 0; w < d; w++)
        s += w2[((f * 64 + g) * d + u) * d + w] * g_C8W[i][off + w * d + m];
    s *= (1.0f / sqrtf(16.0f * d));
    __nv_bfloat16 h, lo; bf16split(s, h, lo);
    g_M2TH[jf][gi] = h; g_M2TL[jf][gi] = lo;
}

// ============ main: proj_1 ============
__global__ void k_featin(const float* traj, const float* w1_0, const float* w1_1) {
    int r = blockIdx.x * blockDim.x + threadIdx.x;
    if (r >= 8192) return;
    int bt = r >> 4, f = r & 15;
    const float* tr = traj + bt * 10;
    g_featin[r][0] = tr[9] * w1_0[f];
    const float inv3 = 0.57735026918962576f;
    #pragma unroll
    for (int w = 0; w < 3; w++)
        #pragma unroll
        for (int m = 0; m < 3; m++) {
            float s = 0.f;
            #pragma unroll
            for (int u = 0; u < 3; u++) s += tr[u * 3 + m] * w1_1[(f * 3 + u) * 3 + w];
            g_featin[r][1 + w * 3 + m] = s * inv3;
        }
}

// ============ main: grid synthesis + relu*sqrt2 -> sig (bf16 split) ============
__global__ void k_gemm1() {
    __shared__ float Fs[64][10];
    __shared__ float Ds[128][10];
    int g0 = blockIdx.x * 128, r0 = blockIdx.y * 64;
    int t = threadIdx.x;
    for (int idx = t; idx < 640; idx += 256) Fs[idx / 10][idx % 10] = g_featin[r0 + idx / 10][idx % 10];
    for (int idx = t; idx < 1280; idx += 256) Ds[idx / 10][idx % 10] = g_DIN[g0 + idx / 10][idx % 10];
    __syncthreads();
    int gl = t & 127, half = t >> 7;
    float dv[10];
    #pragma unroll
    for (int i = 0; i < 10; i++) dv[i] = Ds[gl][i];
    #pragma unroll 4
    for (int rr = half * 32; rr < half * 32 + 32; rr++) {
        float s = 0.f;
        #pragma unroll
        for (int i = 0; i < 10; i++) s += Fs[rr][i] * dv[i];
        s = fmaxf(s, 0.0f) * 1.41421356237309515f;
        __nv_bfloat16 h, lo; bf16split(s, h, lo);
        g_sigH[r0 + rr][g0 + gl] = h;
        g_sigL[r0 + rr][g0 + gl] = lo;
    }
}

// smem layout constants (in halves) for pipelined GEMMs
#define A_HL  (128 * 40)
#define A_BUF (2 * A_HL)
#define B_REG (2 * A_BUF)       // start of B region
#define B_HL  (32 * 72)
#define B_BUF (2 * B_HL)
#define SMEM_GEMM_BYTES ((2 * A_BUF + 2 * B_BUF) * 2)  // 59392

// ============ main: GEMM2 (tensor, cp.async pipelined) feat = sig @ D_OUTW ============
__global__ __launch_bounds__(256) void k_gemm2t() {
    extern __shared__ __align__(16) __nv_bfloat16 sm[];
    unsigned aB = smem_u32(sm);
    unsigned bB = aB + B_REG * 2;
    int m0 = blockIdx.y * 128, n0 = blockIdx.x * 64;
    int t = threadIdx.x, lane = t & 31, wid = t >> 5;
    int wm = (wid & 3) * 32, wn = (wid >> 2) * 32;
    float acc[2][4][4] = {};

    int pr0 = t >> 2, pc0 = (t & 3) * 8;            // A-load coords (v=0)
    int pr1 = (t + 256) >> 2, pc1 = ((t + 256) & 3) * 8;
    int br = t >> 3, bc = (t & 7) * 8;              // B-load coords

    // prefetch iteration it into buffer buf
    #define PF2(it, buf) do {                                               \
        int k0 = (it) * 32;                                                  \
        unsigned d0 = aB + ((buf) * A_BUF + pr0 * 40 + pc0) * 2;             \
        cp16(d0,            &g_sigH[m0 + pr0][k0 + pc0]);                    \
        cp16(d0 + A_HL * 2, &g_sigL[m0 + pr0][k0 + pc0]);                    \
        unsigned d1 = aB + ((buf) * A_BUF + pr1 * 40 + pc1) * 2;             \
        cp16(d1,            &g_sigH[m0 + pr1][k0 + pc1]);                    \
        cp16(d1 + A_HL * 2, &g_sigL[m0 + pr1][k0 + pc1]);                    \
        unsigned d2 = bB + ((buf) * B_BUF + br * 72 + bc) * 2;               \
        cp16(d2,            &g_DWH[k0 + br][n0 + bc]);                       \
        cp16(d2 + B_HL * 2, &g_DWL[k0 + br][n0 + bc]);                       \
    } while (0)

    PF2(0, 0); CP_COMMIT;
    for (int it = 0; it < 64; it++) {
        int buf = it & 1;
        if (it < 63) PF2(it + 1, buf ^ 1);
        CP_COMMIT;
        CP_WAIT1;
        __syncthreads();
        unsigned aBase = aB + buf * A_BUF * 2;
        unsigned bBase = bB + buf * B_BUF * 2;
        #pragma unroll
        for (int ks = 0; ks < 2; ks++) {
            unsigned ah[2][4], al[2][4], bh[2][4], bl[2][4];
            #pragma unroll
            for (int mt = 0; mt < 2; mt++) {
                unsigned off = ((wm + mt * 16 + (lane & 15)) * 40 + ks * 16 + ((lane >> 4) * 8)) * 2;
                ldsm_x4(aBase + off, ah[mt][0], ah[mt][1], ah[mt][2], ah[mt][3]);
                ldsm_x4(aBase + off + A_HL * 2, al[mt][0], al[mt][1], al[mt][2], al[mt][3]);
            }
            #pragma unroll
            for (int p = 0; p < 2; p++) {
                unsigned off = ((ks * 16 + (lane & 15)) * 72 + wn + p * 16 + ((lane >> 4) * 8)) * 2;
                ldsm_x4_t(bBase + off, bh[p][0], bh[p][1], bh[p][2], bh[p][3]);
                ldsm_x4_t(bBase + off + B_HL * 2, bl[p][0], bl[p][1], bl[p][2], bl[p][3]);
            }
            #pragma unroll
            for (int mt = 0; mt < 2; mt++)
                #pragma unroll
                for (int nt = 0; nt < 4; nt++) {
                    int p = nt >> 1, q = (nt & 1) * 2;
                    mma16816(acc[mt][nt], ah[mt], bh[p][q], bh[p][q + 1]);
                    mma16816(acc[mt][nt], al[mt], bh[p][q], bh[p][q + 1]);
                    mma16816(acc[mt][nt], ah[mt], bl[p][q], bl[p][q + 1]);
                }
        }
        __syncthreads();
    }
    int rr = lane >> 2, cc = (lane & 3) * 2;
    #pragma unroll
    for (int mt = 0; mt < 2; mt++)
        #pragma unroll
        for (int nt = 0; nt < 4; nt++) {
            int grow = m0 + wm + mt * 16 + rr;
            int gcol = n0 + wn + nt * 8 + cc;
            if (gcol < JP) {
                __nv_bfloat16 h, lo;
                bf16split(acc[mt][nt][0], h, lo); g_featH[grow][gcol] = h;     g_featL[grow][gcol] = lo;
                bf16split(acc[mt][nt][1], h, lo); g_featH[grow][gcol + 1] = h; g_featL[grow][gcol + 1] = lo;
                bf16split(acc[mt][nt][2], h, lo); g_featH[grow + 8][gcol] = h;     g_featL[grow + 8][gcol] = lo;
                bf16split(acc[mt][nt][3], h, lo); g_featH[grow + 8][gcol + 1] = h; g_featL[grow + 8][gcol + 1] = lo;
            }
        }
}

// ============ main: GEMM3 (tensor, cp.async pipelined, split-K) ============
__global__ __launch_bounds__(256) void k_gemm3t() {
    extern __shared__ __align__(16) __nv_bfloat16 sm[];
    unsigned aB = smem_u32(sm);
    unsigned bB = aB + B_REG * 2;
    int m0 = blockIdx.y * 128, n0 = blockIdx.x * 64, sp = blockIdx.z;
    int kbeg = sp * 1824;
    int t = threadIdx.x, lane = t & 31, wid = t >> 5;
    int wm = (wid & 3) * 32, wn = (wid >> 2) * 32;
    float acc[2][4][4] = {};

    int pr0 = t >> 2, pc0 = (t & 3) * 8;
    int pr1 = (t + 256) >> 2, pc1 = ((t + 256) & 3) * 8;
    int br = t >> 3, bc = (t & 7) * 8;

    #define PF3(it, buf) do {                                               \
        int k0 = kbeg + (it) * 32;                                           \
        {   int kk = k0 + pc0; int f = kk / JP, j = kk - f * JP;             \
            int frow = (m0 + pr0) * 16 + f;                                  \
            unsigned d0 = aB + ((buf) * A_BUF + pr0 * 40 + pc0) * 2;         \
            cp16(d0,            &g_featH[frow][j]);                          \
            cp16(d0 + A_HL * 2, &g_featL[frow][j]); }                        \
        {   int kk = k0 + pc1; int f = kk / JP, j = kk - f * JP;             \
            int frow = (m0 + pr1) * 16 + f;                                  \
            unsigned d1 = aB + ((buf) * A_BUF + pr1 * 40 + pc1) * 2;         \
            cp16(d1,            &g_featH[frow][j]);                          \
            cp16(d1 + A_HL * 2, &g_featL[frow][j]); }                        \
        {   unsigned d2 = bB + ((buf) * B_BUF + br * 72 + bc) * 2;           \
            cp16(d2,            &g_M2TH[k0 + br][n0 + bc]);                  \
            cp16(d2 + B_HL * 2, &g_M2TL[k0 + br][n0 + bc]); }                \
    } while (0)

    PF3(0, 0); CP_COMMIT;
    for (int it = 0; it < 57; it++) {
        int buf = it & 1;
        if (it < 56) PF3(it + 1, buf ^ 1);
        CP_COMMIT;
        CP_WAIT1;
        __syncthreads();
        unsigned aBase = aB + buf * A_BUF * 2;
        unsigned bBase = bB + buf * B_BUF * 2;
        #pragma unroll
        for (int ks = 0; ks < 2; ks++) {
            unsigned ah[2][4], al[2][4], bh[2][4], bl[2][4];
            #pragma unroll
            for (int mt = 0; mt < 2; mt++) {
                unsigned off = ((wm + mt * 16 + (lane & 15)) * 40 + ks * 16 + ((lane >> 4) * 8)) * 2;
                ldsm_x4(aBase + off, ah[mt][0], ah[mt][1], ah[mt][2], ah[mt][3]);
                ldsm_x4(aBase + off + A_HL * 2, al[mt][0], al[mt][1], al[mt][2], al[mt][3]);
            }
            #pragma unroll
            for (int p = 0; p < 2; p++) {
                unsigned off = ((ks * 16 + (lane & 15)) * 72 + wn + p * 16 + ((lane >> 4) * 8)) * 2;
                ldsm_x4_t(bBase + off, bh[p][0], bh[p][1], bh[p][2], bh[p][3]);
                ldsm_x4_t(bBase + off + B_HL * 2, bl[p][0], bl[p][1], bl[p][2], bl[p][3]);
            }
            #pragma unroll
            for (int mt = 0; mt < 2; mt++)
                #pragma unroll
                for (int nt = 0; nt < 4; nt++) {
                    int p = nt >> 1, q = (nt & 1) * 2;
                    mma16816(acc[mt][nt], ah[mt], bh[p][q], bh[p][q + 1]);
                    mma16816(acc[mt][nt], al[mt], bh[p][q], bh[p][q + 1]);
                    mma16816(acc[mt][nt], ah[mt], bl[p][q], bl[p][q + 1]);
                }
        }
        __syncthreads();
    }
    int rr = lane >> 2, cc = (lane & 3) * 2;
    #pragma unroll
    for (int mt = 0; mt < 2; mt++)
        #pragma unroll
        for (int nt = 0; nt < 4; nt++) {
            int grow = m0 + wm + mt * 16 + rr;
            int gcol = n0 + wn + nt * 8 + cc;
            g_part[sp][grow][gcol]     = acc[mt][nt][0];
            g_part[sp][grow][gcol + 1] = acc[mt][nt][1];
            g_part[sp][grow + 8][gcol]     = acc[mt][nt][2];
            g_part[sp][grow + 8][gcol + 1] = acc[mt][nt][3];
        }
}

__global__ void k_reduce(float* out_traj) {
    int idx = blockIdx.x * blockDim.x + threadIdx.x;
    if (idx >= 262144) return;
    int bt = idx >> 9, gi = idx & 511;
    float s = 0.f;
    #pragma unroll
    for (int sp = 0; sp < 4; sp++) s += g_part[sp][bt][gi];
    out_traj[idx] = s;
}

// ============ main: x_c8 = x @ C8W^T ============
__global__ void k_xc8(const float* __restrict__ x, float* __restrict__ out) {
    __shared__ float C[8 * 455];
    int t = threadIdx.x;
    for (int idx = t; idx < 3640; idx += 256) C[idx] = g_C8W[idx / 455][idx % 455];
    __syncthreads();
    int warp = t >> 5, lane = t & 31;
    long long row = (long long)blockIdx.x * 8 + warp;
    const float* xr = x + row * 455;
    float acc[8] = {};
    for (int j = lane; j < 455; j += 32) {
        float v = xr[j];
        #pragma unroll
        for (int i = 0; i < 8; i++) acc[i] += v * C[i * 455 + j];
    }
    #pragma unroll
    for (int i = 0; i < 8; i++)
        #pragma unroll
        for (int o = 16; o > 0; o >>= 1) acc[i] += __shfl_xor_sync(0xffffffffu, acc[i], o);
    if (lane == 0) {
        float* o8 = out + row * 8;
        #pragma unroll
        for (int i = 0; i < 8; i++) o8[i] = acc[i];
    }
}

// ================= launch =================
extern "C" void kernel_launch(void* const* d_in, const int* in_sizes, int n_in,
                              void* d_out, int out_size) {
    const float* x    = (const float*)d_in[0];
    const float* traj = (const float*)d_in[1];
    const float* w1_0 = (const float*)d_in[2];
    const float* w1_1 = (const float*)d_in[3];
    const float* w2_0 = (const float*)d_in[4];
    const float* w2_1 = (const float*)d_in[5];
    const float* w2_2 = (const float*)d_in[6];
    const float* w2_3 = (const float*)d_in[7];
    const float* w2_4 = (const float*)d_in[8];
    const float* w2_5 = (const float*)d_in[9];
    const float* w2_6 = (const float*)d_in[10];
    float* out = (float*)d_out;
    float* out_traj = out + 524288;

    cudaFuncSetAttribute(k_gemm2t, cudaFuncAttributeMaxDynamicSharedMemorySize, SMEM_GEMM_BYTES);
    cudaFuncSetAttribute(k_gemm3t, cudaFuncAttributeMaxDynamicSharedMemorySize, SMEM_GEMM_BYTES);

    k_init<<<1, 32>>>();
    k_gen<<<7, 192>>>();
    k_expm<<<336, 192>>>();
    k_fab<<<896, 192>>>();
    k_dout<<<2048, 256>>>();
    k_c8<<<8, 192>>>();
    k_m2<<<K3, 512>>>(w2_0, w2_1, w2_2, w2_3, w2_4, w2_5, w2_6);

    k_featin<<<32, 256>>>(traj, w1_0, w1_1);
    k_gemm1<<<dim3(16, 128), 256>>>();
    k_gemm2t<<<dim3(8, 64), 256, SMEM_GEMM_BYTES>>>();
    k_gemm3t<<<dim3(8, 4, 4), 256, SMEM_GEMM_BYTES>>>();
    k_reduce<<<1024, 256>>>(out_traj);

    k_xc8<<<8192, 256>>>(x, out);
}